// round 4
// baseline (speedup 1.0000x reference)
#include <cuda_runtime.h>

// ---------------------------------------------------------------------------
// ImageFusion (FrequencyTransformer block), fp32 baseline.
// Pipeline:
//   K1 ln_im2col : LN(x) -> im2col A [M=2048, K=2048]
//   K2 gemm_qkv  : Q/K/V = A @ W{q,k,v} + b   (M=2048, N=16384, K=2048) x3
//   K3 attn      : per (patch m, head): 8x8 circular conv of q,k patches
//                  (== irfft2(rfft2(q)*rfft2(k))), LN over DIM, gate by v,
//                  write O [2048, 16384] in final-conv im2col order
//   K4 gemm_out  : Y = O @ Wo + bo, scatter to NHWC + residual x
// ---------------------------------------------------------------------------

#define Bb    2
#define Hh    256
#define Ww    256
#define Cc    32
#define Pp    8
#define HEADS 8
#define DIMc  32
#define Mm    2048      // B*GH*GW patches
#define Kqkv  2048      // P*P*C
#define Ff    16384     // DIM*P*P*HEADS
#define Kfin  16384     // P*P*HEADS*DIM
#define Nfin  2048      // DIM*P*P

// Scratch (static device arrays; no runtime allocation allowed)
__device__ float g_A[Mm * Kqkv];                    //  16 MB
__device__ float g_QKV[3 * Mm * Ff];                // 402 MB
__device__ float g_O[Mm * Kfin];                    // 134 MB

// ---------------------------------------------------------------------------
// K1: LayerNorm over C=32 per pixel + im2col into A[m][k],
//     m = b*1024 + gh*32 + gw,  k = p0*256 + p1*32 + c
// One warp per pixel (lane == channel).
// ---------------------------------------------------------------------------
__global__ void ln_im2col_kernel(const float* __restrict__ x,
                                 const float* __restrict__ gam,
                                 const float* __restrict__ bet) {
    int pix  = (blockIdx.x * blockDim.x + threadIdx.x) >> 5;
    int lane = threadIdx.x & 31;
    if (pix >= Bb * Hh * Ww) return;

    float v = x[(size_t)pix * Cc + lane];
    float mu = v;
#pragma unroll
    for (int o = 16; o; o >>= 1) mu += __shfl_xor_sync(0xffffffffu, mu, o);
    mu *= (1.0f / 32.0f);
    float d = v - mu;
    float var = d * d;
#pragma unroll
    for (int o = 16; o; o >>= 1) var += __shfl_xor_sync(0xffffffffu, var, o);
    var *= (1.0f / 32.0f);
    float xn = d * rsqrtf(var + 1e-6f) * gam[lane] + bet[lane];

    int w = pix % Ww;
    int h = (pix / Ww) % Hh;
    int b = pix / (Ww * Hh);
    int m = b * 1024 + (h >> 3) * 32 + (w >> 3);
    int k = (h & 7) * 256 + (w & 7) * 32 + lane;
    g_A[m * Kqkv + k] = xn;
}

// ---------------------------------------------------------------------------
// K2: Q/K/V GEMM.  C[z] = A @ W[z] + bias[z].  128x128x16 tile, 256 thr, 8x8/thr.
// ---------------------------------------------------------------------------
__global__ void __launch_bounds__(256, 2)
gemm_qkv_kernel(const float* __restrict__ Wq, const float* __restrict__ Wk,
                const float* __restrict__ Wv, const float* __restrict__ bq,
                const float* __restrict__ bk, const float* __restrict__ bv) {
    __shared__ float As[16][132];
    __shared__ float Bs[16][128];
    const int N = Ff, K = Kqkv;

    int z = blockIdx.z;
    const float* Bg   = (z == 0) ? Wq : ((z == 1) ? Wk : Wv);
    const float* bias = (z == 0) ? bq : ((z == 1) ? bk : bv);
    float* Cg = g_QKV + (size_t)z * Mm * Ff;
    const float* Ag = g_A;

    int tid = threadIdx.x;
    int bm = blockIdx.y * 128, bn = blockIdx.x * 128;
    int ar = tid >> 1, ak = (tid & 1) << 3;
    int br = tid >> 4, bc = (tid & 15) << 3;
    int ty = tid >> 4, tx = tid & 15;

    float acc[8][8];
#pragma unroll
    for (int i = 0; i < 8; i++)
#pragma unroll
        for (int j = 0; j < 8; j++) acc[i][j] = 0.f;

    for (int k0 = 0; k0 < K; k0 += 16) {
        float4 a0 = *(const float4*)(Ag + (size_t)(bm + ar) * K + k0 + ak);
        float4 a1 = *(const float4*)(Ag + (size_t)(bm + ar) * K + k0 + ak + 4);
        float4 b0 = *(const float4*)(Bg + (size_t)(k0 + br) * N + bn + bc);
        float4 b1 = *(const float4*)(Bg + (size_t)(k0 + br) * N + bn + bc + 4);
        As[ak + 0][ar] = a0.x; As[ak + 1][ar] = a0.y;
        As[ak + 2][ar] = a0.z; As[ak + 3][ar] = a0.w;
        As[ak + 4][ar] = a1.x; As[ak + 5][ar] = a1.y;
        As[ak + 6][ar] = a1.z; As[ak + 7][ar] = a1.w;
        *(float4*)&Bs[br][bc]     = b0;
        *(float4*)&Bs[br][bc + 4] = b1;
        __syncthreads();
#pragma unroll
        for (int kk = 0; kk < 16; kk++) {
            float4 av0 = *(const float4*)&As[kk][ty * 8];
            float4 av1 = *(const float4*)&As[kk][ty * 8 + 4];
            float4 bv0 = *(const float4*)&Bs[kk][tx * 8];
            float4 bv1 = *(const float4*)&Bs[kk][tx * 8 + 4];
            float a[8] = {av0.x, av0.y, av0.z, av0.w, av1.x, av1.y, av1.z, av1.w};
            float bb[8] = {bv0.x, bv0.y, bv0.z, bv0.w, bv1.x, bv1.y, bv1.z, bv1.w};
#pragma unroll
            for (int i = 0; i < 8; i++)
#pragma unroll
                for (int j = 0; j < 8; j++) acc[i][j] += a[i] * bb[j];
        }
        __syncthreads();
    }

#pragma unroll
    for (int i = 0; i < 8; i++) {
        int r = bm + ty * 8 + i;
        float* crow = Cg + (size_t)r * N + bn + tx * 8;
#pragma unroll
        for (int j = 0; j < 8; j++) crow[j] = acc[i][j] + bias[bn + tx * 8 + j];
    }
}

// ---------------------------------------------------------------------------
// K3: per (m, head): circular conv of q,k 8x8 patches (all 32 c), LN over c,
//     gate by v, write O[m][p0*2048 + p1*256 + head*32 + c].
// QKV row layout: f = c*512 + p0*64 + p1*8 + head.
// ---------------------------------------------------------------------------
__global__ void __launch_bounds__(256)
attn_kernel(const float* __restrict__ l2s, const float* __restrict__ l2b) {
    __shared__ float qs[32 * 64];
    __shared__ float ks[32 * 64];
    __shared__ float vs[32 * 65];    // padded: [c][65]
    __shared__ float outs[32 * 65];  // padded: [c][65]
    __shared__ float s2[32], b2[32], mus[64], rstds[64];

    int m = blockIdx.x;
    int head = blockIdx.y;
    int tid = threadIdx.x;

    const float* Q  = g_QKV + (size_t)0 * Mm * Ff + (size_t)m * Ff;
    const float* Kp = g_QKV + (size_t)1 * Mm * Ff + (size_t)m * Ff;
    const float* V  = g_QKV + (size_t)2 * Mm * Ff + (size_t)m * Ff;

    if (tid < 32) { s2[tid] = l2s[tid]; b2[tid] = l2b[tid]; }

#pragma unroll
    for (int it = 0; it < 8; it++) {
        int idx = it * 256 + tid;            // 0..2047, pos-fastest
        int c = idx >> 6, pos = idx & 63;
        int p0 = pos >> 3, p1 = pos & 7;
        int f = c * 512 + p0 * 64 + p1 * 8 + head;
        qs[idx] = Q[f];
        ks[idx] = Kp[f];
        vs[c * 65 + pos] = V[f];
    }
    __syncthreads();

    // circular convolution: out[c][s][t] = sum_{u,v} q[c][u][v] * k[c][(s-u)&7][(t-v)&7]
    float res[8];
#pragma unroll
    for (int j = 0; j < 8; j++) {
        int idx = j * 256 + tid;
        int c = idx >> 6, pos = idx & 63;
        int s = pos >> 3, t = pos & 7;
        const float* qc = &qs[c * 64];
        const float* kc = &ks[c * 64];
        float sum = 0.f;
#pragma unroll
        for (int u = 0; u < 8; u++) {
            int su = ((s - u) & 7) * 8;
#pragma unroll
            for (int v = 0; v < 8; v++)
                sum += qc[u * 8 + v] * kc[su + ((t - v) & 7)];
        }
        res[j] = sum;
    }
#pragma unroll
    for (int j = 0; j < 8; j++) {
        int idx = j * 256 + tid;
        int c = idx >> 6, pos = idx & 63;
        outs[c * 65 + pos] = res[j];
    }
    __syncthreads();

    // LN over c per position
    if (tid < 64) {
        float mu = 0.f;
#pragma unroll
        for (int c = 0; c < 32; c++) mu += outs[c * 65 + tid];
        mu *= (1.0f / 32.0f);
        float var = 0.f;
#pragma unroll
        for (int c = 0; c < 32; c++) {
            float d = outs[c * 65 + tid] - mu;
            var += d * d;
        }
        var *= (1.0f / 32.0f);
        mus[tid] = mu;
        rstds[tid] = rsqrtf(var + 1e-6f);
    }
    __syncthreads();

    // gate by v, write O (c-fastest for coalesced global stores)
    float* Orow = g_O + (size_t)m * Kfin;
#pragma unroll
    for (int it = 0; it < 8; it++) {
        int idx = it * 256 + tid;
        int c = idx & 31, pos = idx >> 5;
        int p0 = pos >> 3, p1 = pos & 7;
        float val = (outs[c * 65 + pos] - mus[pos]) * rstds[pos] * s2[c] + b2[c];
        Orow[p0 * 2048 + p1 * 256 + head * 32 + c] = vs[c * 65 + pos] * val;
    }
}

// ---------------------------------------------------------------------------
// K4: final GEMM Y = O @ Wo + bo, scatter to NHWC + residual.
// ---------------------------------------------------------------------------
__global__ void __launch_bounds__(256, 2)
gemm_out_kernel(const float* __restrict__ Wo, const float* __restrict__ bo,
                const float* __restrict__ xin, float* __restrict__ out) {
    __shared__ float As[16][132];
    __shared__ float Bs[16][128];
    const int N = Nfin, K = Kfin;
    const float* Ag = g_O;
    const float* Bg = Wo;

    int tid = threadIdx.x;
    int bm = blockIdx.y * 128, bn = blockIdx.x * 128;
    int ar = tid >> 1, ak = (tid & 1) << 3;
    int br = tid >> 4, bc = (tid & 15) << 3;
    int ty = tid >> 4, tx = tid & 15;

    float acc[8][8];
#pragma unroll
    for (int i = 0; i < 8; i++)
#pragma unroll
        for (int j = 0; j < 8; j++) acc[i][j] = 0.f;

    for (int k0 = 0; k0 < K; k0 += 16) {
        float4 a0 = *(const float4*)(Ag + (size_t)(bm + ar) * K + k0 + ak);
        float4 a1 = *(const float4*)(Ag + (size_t)(bm + ar) * K + k0 + ak + 4);
        float4 b0 = *(const float4*)(Bg + (size_t)(k0 + br) * N + bn + bc);
        float4 b1 = *(const float4*)(Bg + (size_t)(k0 + br) * N + bn + bc + 4);
        As[ak + 0][ar] = a0.x; As[ak + 1][ar] = a0.y;
        As[ak + 2][ar] = a0.z; As[ak + 3][ar] = a0.w;
        As[ak + 4][ar] = a1.x; As[ak + 5][ar] = a1.y;
        As[ak + 6][ar] = a1.z; As[ak + 7][ar] = a1.w;
        *(float4*)&Bs[br][bc]     = b0;
        *(float4*)&Bs[br][bc + 4] = b1;
        __syncthreads();
#pragma unroll
        for (int kk = 0; kk < 16; kk++) {
            float4 av0 = *(const float4*)&As[kk][ty * 8];
            float4 av1 = *(const float4*)&As[kk][ty * 8 + 4];
            float4 bv0 = *(const float4*)&Bs[kk][tx * 8];
            float4 bv1 = *(const float4*)&Bs[kk][tx * 8 + 4];
            float a[8] = {av0.x, av0.y, av0.z, av0.w, av1.x, av1.y, av1.z, av1.w};
            float bb[8] = {bv0.x, bv0.y, bv0.z, bv0.w, bv1.x, bv1.y, bv1.z, bv1.w};
#pragma unroll
            for (int i = 0; i < 8; i++)
#pragma unroll
                for (int j = 0; j < 8; j++) acc[i][j] += a[i] * bb[j];
        }
        __syncthreads();
    }

    // epilogue: f2 = c*64 + p0*8 + p1, out[b, gh*8+p0, gw*8+p1, c] = y + x
#pragma unroll
    for (int i = 0; i < 8; i++) {
        int r = bm + ty * 8 + i;
        int b_ = r >> 10, gh = (r >> 5) & 31, gw = r & 31;
#pragma unroll
        for (int j = 0; j < 8; j++) {
            int f2 = bn + tx * 8 + j;
            int c = f2 >> 6, p0 = (f2 >> 3) & 7, p1 = f2 & 7;
            size_t oi = (((size_t)(b_ * Hh + gh * 8 + p0)) * Ww + gw * 8 + p1) * Cc + c;
            out[oi] = acc[i][j] + bo[f2] + xin[oi];
        }
    }
}

// ---------------------------------------------------------------------------
extern "C" void kernel_launch(void* const* d_in, const int* in_sizes, int n_in,
                              void* d_out, int out_size) {
    const float* x   = (const float*)d_in[0];
    const float* l1s = (const float*)d_in[1];
    const float* l1b = (const float*)d_in[2];
    const float* Wq  = (const float*)d_in[3];
    const float* bq  = (const float*)d_in[4];
    const float* Wk  = (const float*)d_in[5];
    const float* bk  = (const float*)d_in[6];
    const float* Wv  = (const float*)d_in[7];
    const float* bv  = (const float*)d_in[8];
    const float* l2s = (const float*)d_in[9];
    const float* l2b = (const float*)d_in[10];
    const float* Wo  = (const float*)d_in[11];
    const float* bo  = (const float*)d_in[12];
    float* out = (float*)d_out;

    // K1: LN + im2col (131072 pixels, warp per pixel)
    ln_im2col_kernel<<<(Bb * Hh * Ww * 32) / 256, 256>>>(x, l1s, l1b);

    // K2: Q/K/V GEMMs
    dim3 gq(Ff / 128, Mm / 128, 3);
    gemm_qkv_kernel<<<gq, 256>>>(Wq, Wk, Wv, bq, bk, bv);

    // K3: circular-conv "attention" + LN + gate
    dim3 ga(Mm, HEADS);
    attn_kernel<<<ga, 256>>>(l2s, l2b);

    // K4: output GEMM + scatter + residual
    dim3 go(Nfin / 128, Mm / 128);
    gemm_out_kernel<<<go, 256>>>(Wo, bo, x, out);
}

// round 6
// speedup vs baseline: 1.8915x; 1.8915x over previous
#include <cuda_runtime.h>
#include <cuda_bf16.h>
#include <cstdint>

// ---------------------------------------------------------------------------
// ImageFusion via mma.sync bf16 GEMMs with hi/lo fp32-split, tripled-K trick:
//   A'' = [Ah | Ah | Al],  B'' = [Bh | Bl | Bh]  =>  A''@B''^T = AhBh+AhBl+AlBh
// Base-ISA only (no tcgen05 — ptxas targets sm_103 without 'a' features).
//   K0 transpose_split : W[K][N] fp32 -> W''[N][3K] bf16
//   K1 ln_im2col       : LN(x) -> A''[2048][6144] bf16
//   K2 gemm_qkv        : QKV fp32 = A'' @ W''^T + b   (mma.sync bf16)
//   K3 attn            : 8x8 circular conv + LN + gate -> O''[2048][49152] bf16
//   K4 gemm_out        : Y = O'' @ Wo''^T + bo, scatter NHWC + residual
// ---------------------------------------------------------------------------

#define Bb    2
#define Hh    256
#define Ww    256
#define Cc    32
#define HEADS 8
#define Mm    2048
#define Kq    2048
#define K2g   (3 * Kq)     // 6144
#define Ff    16384
#define Kf    16384
#define K4g   (3 * Kf)     // 49152
#define Nfin  2048

// ---- scratch (static device arrays) ----
__device__ __align__(1024) __nv_bfloat16 g_A2[(size_t)Mm * K2g];       //  25 MB
__device__ __align__(1024) __nv_bfloat16 g_W2[(size_t)3 * Ff * K2g];   // 604 MB
__device__ __align__(1024) __nv_bfloat16 g_Wo2[(size_t)Nfin * K4g];    // 201 MB
__device__ float                          g_QKV[(size_t)3 * Mm * Ff];  // 402 MB
__device__ __align__(1024) __nv_bfloat16 g_O2[(size_t)Mm * K4g];       // 201 MB

// ---------------------------------------------------------------------------
// helpers
// ---------------------------------------------------------------------------
static __device__ __forceinline__ uint32_t s2u(const void* p) {
    uint32_t a;
    asm("{ .reg .u64 t; cvta.to.shared.u64 t, %1; cvt.u32.u64 %0, t; }"
        : "=r"(a) : "l"(p));
    return a;
}
static __device__ __forceinline__ void cpa16(uint32_t dst, const void* src) {
    asm volatile("cp.async.cg.shared.global [%0], [%1], 16;\n"
                 :: "r"(dst), "l"(src));
}
static __device__ __forceinline__ void cpa_commit() {
    asm volatile("cp.async.commit_group;\n");
}
template <int N>
static __device__ __forceinline__ void cpa_wait() {
    asm volatile("cp.async.wait_group %0;\n" :: "n"(N));
}
static __device__ __forceinline__ void ldm4(uint32_t* r, uint32_t a) {
    asm volatile("ldmatrix.sync.aligned.m8n8.x4.shared.b16 {%0,%1,%2,%3}, [%4];"
                 : "=r"(r[0]), "=r"(r[1]), "=r"(r[2]), "=r"(r[3]) : "r"(a));
}
static __device__ __forceinline__ void mma16816(float* d, const uint32_t* a,
                                                uint32_t b0, uint32_t b1) {
    asm volatile("mma.sync.aligned.m16n8k16.row.col.f32.bf16.bf16.f32 "
                 "{%0,%1,%2,%3}, {%4,%5,%6,%7}, {%8,%9}, {%0,%1,%2,%3};"
                 : "+f"(d[0]), "+f"(d[1]), "+f"(d[2]), "+f"(d[3])
                 : "r"(a[0]), "r"(a[1]), "r"(a[2]), "r"(a[3]), "r"(b0), "r"(b1));
}

// ---------------------------------------------------------------------------
// GEMM core: BM=128, BN=128, BK=64, 256 threads, 3-stage cp.async pipeline.
// SMEM tile layout: 16x16 bf16 atoms (512B each), atom (ka, i) at
// (ka*8+i)*512; element (row, col16) at row*32 + ((col>>3 ^ (row>>2)&1)<<4)
// + (col&7)*2.  This makes both cp.async stores and ldmatrix loads
// conflict-free.
// ---------------------------------------------------------------------------
#define STG_A   16384
#define STG_SZ  32768
#define NSTAGE  3
#define GSMEM   (NSTAGE * STG_SZ)

static __device__ __forceinline__ void load_stage(const __nv_bfloat16* gA,
                                                  const __nv_bfloat16* gB,
                                                  int Kg, uint32_t base, int k0,
                                                  int tid) {
#pragma unroll
    for (int it = 0; it < 4; it++) {           // A: 128 rows x 8 16B-chunks
        int q = it * 256 + tid;
        int m = q >> 3, h2 = q & 7;
        uint32_t dst = base + ((h2 >> 1) * 8 + (m >> 4)) * 512 + (m & 15) * 32
                     + ((((h2 & 1)) ^ ((m >> 2) & 1)) << 4);
        cpa16(dst, gA + (size_t)m * Kg + k0 + (h2 << 3));
    }
#pragma unroll
    for (int it = 0; it < 4; it++) {           // B: 128 rows x 8 16B-chunks
        int q = it * 256 + tid;
        int n = q >> 3, h2 = q & 7;
        uint32_t dst = base + STG_A + ((h2 >> 1) * 8 + (n >> 4)) * 512
                     + (n & 15) * 32 + ((((h2 & 1)) ^ ((n >> 2) & 1)) << 4);
        cpa16(dst, gB + (size_t)n * Kg + k0 + (h2 << 3));
    }
}

static __device__ __forceinline__ void compute_stage(uint32_t sbase, int wm, int wn,
                                                     uint32_t inAtom,
                                                     float acc[2][8][4]) {
    uint32_t abase = sbase + wm * 2 * 512 + inAtom;           // 2 m-atoms / warp
    uint32_t bbase = sbase + STG_A + wn * 4 * 512 + inAtom;   // 4 n-atoms / warp
#pragma unroll
    for (int ks = 0; ks < 4; ks++) {                          // BK/16
        uint32_t af[2][4], bf[4][4];
#pragma unroll
        for (int am = 0; am < 2; am++) ldm4(af[am], abase + ks * 4096 + am * 512);
#pragma unroll
        for (int bi = 0; bi < 4; bi++) ldm4(bf[bi], bbase + ks * 4096 + bi * 512);
#pragma unroll
        for (int am = 0; am < 2; am++)
#pragma unroll
            for (int bi = 0; bi < 4; bi++) {
                mma16816(acc[am][bi * 2 + 0], af[am], bf[bi][0], bf[bi][2]);
                mma16816(acc[am][bi * 2 + 1], af[am], bf[bi][1], bf[bi][3]);
            }
    }
}

static __device__ __forceinline__ void gemm_mainloop(const __nv_bfloat16* gA,
                                                     const __nv_bfloat16* gB,
                                                     int Kg, int niter,
                                                     uint32_t sb,
                                                     float acc[2][8][4]) {
    int tid = threadIdx.x, lane = tid & 31, wid = tid >> 5;
    int wm = wid >> 1, wn = wid & 1;
    int quad = lane >> 3;
    int lrow = ((quad & 1) << 3) + (lane & 7);
    int half = quad >> 1;
    uint32_t inAtom = lrow * 32 + ((half ^ ((lrow >> 2) & 1)) << 4);

#pragma unroll
    for (int am = 0; am < 2; am++)
#pragma unroll
        for (int ni = 0; ni < 8; ni++)
#pragma unroll
            for (int j = 0; j < 4; j++) acc[am][ni][j] = 0.f;

    load_stage(gA, gB, Kg, sb, 0, tid);             cpa_commit();
    load_stage(gA, gB, Kg, sb + STG_SZ, 64, tid);   cpa_commit();

    for (int i = 0; i < niter; i++) {
        if (i + 1 < niter) cpa_wait<1>(); else cpa_wait<0>();
        __syncthreads();
        if (i + 2 < niter) {
            load_stage(gA, gB, Kg, sb + ((i + 2) % 3) * STG_SZ, (i + 2) * 64, tid);
            cpa_commit();
        }
        compute_stage(sb + (i % 3) * STG_SZ, wm, wn, inAtom, acc);
    }
}

// ---------------------------------------------------------------------------
// K0: transpose + split: src fp32 [R][C] -> dst bf16 [C][3R] = [hi | lo | hi]
// ---------------------------------------------------------------------------
__global__ void __launch_bounds__(256)
transpose_split_kernel(const float* __restrict__ src,
                       __nv_bfloat16* __restrict__ dst, int R, int C) {
    __shared__ float t[32][33];
    int tx = threadIdx.x, ty = threadIdx.y;
    int c0 = blockIdx.x * 32, r0 = blockIdx.y * 32;
#pragma unroll
    for (int i = 0; i < 4; i++)
        t[ty + i * 8][tx] = src[(size_t)(r0 + ty + i * 8) * C + c0 + tx];
    __syncthreads();
#pragma unroll
    for (int i = 0; i < 4; i++) {
        float v = t[tx][ty + i * 8];
        size_t base = (size_t)(c0 + ty + i * 8) * (3 * R) + r0 + tx;
        __nv_bfloat16 h = __float2bfloat16(v);
        __nv_bfloat16 l = __float2bfloat16(v - __bfloat162float(h));
        dst[base]         = h;
        dst[base + R]     = l;
        dst[base + 2 * R] = h;
    }
}

// ---------------------------------------------------------------------------
// K1: LN over C=32 per pixel + im2col -> A'' [hi | hi | lo]
// ---------------------------------------------------------------------------
__global__ void ln_im2col_kernel(const float* __restrict__ x,
                                 const float* __restrict__ gam,
                                 const float* __restrict__ bet) {
    int pix  = (blockIdx.x * blockDim.x + threadIdx.x) >> 5;
    int lane = threadIdx.x & 31;
    if (pix >= Bb * Hh * Ww) return;

    float v = x[(size_t)pix * Cc + lane];
    float mu = v;
#pragma unroll
    for (int o = 16; o; o >>= 1) mu += __shfl_xor_sync(0xffffffffu, mu, o);
    mu *= (1.0f / 32.0f);
    float d = v - mu;
    float var = d * d;
#pragma unroll
    for (int o = 16; o; o >>= 1) var += __shfl_xor_sync(0xffffffffu, var, o);
    var *= (1.0f / 32.0f);
    float xn = d * rsqrtf(var + 1e-6f) * gam[lane] + bet[lane];

    int w = pix % Ww;
    int h = (pix / Ww) % Hh;
    int b = pix / (Ww * Hh);
    int m = b * 1024 + (h >> 3) * 32 + (w >> 3);
    int k = (h & 7) * 256 + (w & 7) * 32 + lane;
    size_t o = (size_t)m * K2g + k;
    __nv_bfloat16 hi = __float2bfloat16(xn);
    __nv_bfloat16 lo = __float2bfloat16(xn - __bfloat162float(hi));
    g_A2[o]            = hi;
    g_A2[o + Kq]       = hi;
    g_A2[o + 2 * Kq]   = lo;
}

// ---------------------------------------------------------------------------
// K2: Q/K/V GEMM.  grid (16, 128, 3): bm = x*128, bn = y*128 (column-major
// rasterization: 16 consecutive CTAs share bn -> B tile L2 reuse).
// ---------------------------------------------------------------------------
__global__ void __launch_bounds__(256, 2)
gemm_qkv_kernel(const float* __restrict__ bq, const float* __restrict__ bk,
                const float* __restrict__ bv) {
    extern __shared__ char smem[];
    uint32_t sb = s2u(smem);
    int tid = threadIdx.x, lane = tid & 31, wid = tid >> 5;
    int wm = wid >> 1, wn = wid & 1;
    int bm = blockIdx.x * 128, bn = blockIdx.y * 128, z = blockIdx.z;

    const __nv_bfloat16* gA = g_A2 + (size_t)bm * K2g;
    const __nv_bfloat16* gB = g_W2 + ((size_t)z * Ff + bn) * K2g;

    float acc[2][8][4];
    gemm_mainloop(gA, gB, K2g, K2g / 64, sb, acc);

    const float* bias = (z == 0) ? bq : ((z == 1) ? bk : bv);
    float* Cg = g_QKV + (size_t)z * Mm * Ff;
    int g = lane >> 2, t = lane & 3;
#pragma unroll
    for (int am = 0; am < 2; am++) {
        int row = bm + wm * 32 + am * 16 + g;
#pragma unroll
        for (int ni = 0; ni < 8; ni++) {
            int col = bn + wn * 64 + ni * 8 + t * 2;
            float2 bi2 = *(const float2*)(bias + col);
            float2 o0, o1;
            o0.x = acc[am][ni][0] + bi2.x;  o0.y = acc[am][ni][1] + bi2.y;
            o1.x = acc[am][ni][2] + bi2.x;  o1.y = acc[am][ni][3] + bi2.y;
            *(float2*)(Cg + (size_t)row * Ff + col)       = o0;
            *(float2*)(Cg + (size_t)(row + 8) * Ff + col) = o1;
        }
    }
}

// ---------------------------------------------------------------------------
// K3: attention (8x8 circular conv) + LN + gate -> O'' [hi | hi | lo]
// ---------------------------------------------------------------------------
__global__ void __launch_bounds__(256)
attn_kernel(const float* __restrict__ l2s, const float* __restrict__ l2b) {
    __shared__ float qs[32 * 64];
    __shared__ float ks[32 * 64];
    __shared__ float vs[32 * 65];
    __shared__ float outs[32 * 65];
    __shared__ float s2[32], b2[32], mus[64], rstds[64];

    int m = blockIdx.x;
    int head = blockIdx.y;
    int tid = threadIdx.x;

    const float* Q  = g_QKV + (size_t)m * Ff;
    const float* Kp = g_QKV + (size_t)Mm * Ff + (size_t)m * Ff;
    const float* V  = g_QKV + (size_t)2 * Mm * Ff + (size_t)m * Ff;

    if (tid < 32) { s2[tid] = l2s[tid]; b2[tid] = l2b[tid]; }

#pragma unroll
    for (int it = 0; it < 8; it++) {
        int idx = it * 256 + tid;
        int c = idx >> 6, pos = idx & 63;
        int p0 = pos >> 3, p1 = pos & 7;
        int f = c * 512 + p0 * 64 + p1 * 8 + head;
        qs[idx] = Q[f];
        ks[idx] = Kp[f];
        vs[c * 65 + pos] = V[f];
    }
    __syncthreads();

    float res[8];
#pragma unroll
    for (int j = 0; j < 8; j++) {
        int idx = j * 256 + tid;
        int c = idx >> 6, pos = idx & 63;
        int s = pos >> 3, t = pos & 7;
        const float* qc = &qs[c * 64];
        const float* kc = &ks[c * 64];
        float sum = 0.f;
#pragma unroll
        for (int u = 0; u < 8; u++) {
            int su = ((s - u) & 7) * 8;
#pragma unroll
            for (int v = 0; v < 8; v++)
                sum += qc[u * 8 + v] * kc[su + ((t - v) & 7)];
        }
        res[j] = sum;
    }
#pragma unroll
    for (int j = 0; j < 8; j++) {
        int idx = j * 256 + tid;
        int c = idx >> 6, pos = idx & 63;
        outs[c * 65 + pos] = res[j];
    }
    __syncthreads();

    if (tid < 64) {
        float mu = 0.f;
#pragma unroll
        for (int c = 0; c < 32; c++) mu += outs[c * 65 + tid];
        mu *= (1.0f / 32.0f);
        float var = 0.f;
#pragma unroll
        for (int c = 0; c < 32; c++) {
            float d = outs[c * 65 + tid] - mu;
            var += d * d;
        }
        var *= (1.0f / 32.0f);
        mus[tid] = mu;
        rstds[tid] = rsqrtf(var + 1e-6f);
    }
    __syncthreads();

    size_t Obase = (size_t)m * K4g;
#pragma unroll
    for (int it = 0; it < 8; it++) {
        int idx = it * 256 + tid;
        int c = idx & 31, pos = idx >> 5;
        int p0 = pos >> 3, p1 = pos & 7;
        float val = (outs[c * 65 + pos] - mus[pos]) * rstds[pos] * s2[c] + b2[c];
        float prod = vs[c * 65 + pos] * val;
        size_t o = Obase + p0 * 2048 + p1 * 256 + head * 32 + c;
        __nv_bfloat16 h = __float2bfloat16(prod);
        __nv_bfloat16 l = __float2bfloat16(prod - __bfloat162float(h));
        g_O2[o]          = h;
        g_O2[o + Kf]     = h;
        g_O2[o + 2 * Kf] = l;
    }
}

// ---------------------------------------------------------------------------
// K4: output GEMM + scatter + residual. grid (16, 16).
// ---------------------------------------------------------------------------
__global__ void __launch_bounds__(256, 2)
gemm_out_kernel(const float* __restrict__ bo, const float* __restrict__ xin,
                float* __restrict__ out) {
    extern __shared__ char smem[];
    uint32_t sb = s2u(smem);
    int tid = threadIdx.x, lane = tid & 31, wid = tid >> 5;
    int wm = wid >> 1, wn = wid & 1;
    int bm = blockIdx.x * 128, bn = blockIdx.y * 128;

    const __nv_bfloat16* gA = g_O2 + (size_t)bm * K4g;
    const __nv_bfloat16* gB = g_Wo2 + (size_t)bn * K4g;

    float acc[2][8][4];
    gemm_mainloop(gA, gB, K4g, K4g / 64, sb, acc);

    int g = lane >> 2, t = lane & 3;
#pragma unroll
    for (int am = 0; am < 2; am++) {
#pragma unroll
        for (int ni = 0; ni < 8; ni++) {
#pragma unroll
            for (int rr = 0; rr < 2; rr++) {
                int row = bm + wm * 32 + am * 16 + g + rr * 8;
                int b_ = row >> 10, gh = (row >> 5) & 31, gw = row & 31;
#pragma unroll
                for (int jj = 0; jj < 2; jj++) {
                    int f2 = bn + wn * 64 + ni * 8 + t * 2 + jj;
                    int c = f2 >> 6, p0 = (f2 >> 3) & 7, p1 = f2 & 7;
                    size_t oi = (((size_t)(b_ * Hh + gh * 8 + p0)) * Ww
                                 + gw * 8 + p1) * Cc + c;
                    out[oi] = acc[am][ni][rr * 2 + jj] + bo[f2] + xin[oi];
                }
            }
        }
    }
}

// ---------------------------------------------------------------------------
extern "C" void kernel_launch(void* const* d_in, const int* in_sizes, int n_in,
                              void* d_out, int out_size) {
    const float* x   = (const float*)d_in[0];
    const float* l1s = (const float*)d_in[1];
    const float* l1b = (const float*)d_in[2];
    const float* Wq  = (const float*)d_in[3];
    const float* bq  = (const float*)d_in[4];
    const float* Wk  = (const float*)d_in[5];
    const float* bk  = (const float*)d_in[6];
    const float* Wv  = (const float*)d_in[7];
    const float* bv  = (const float*)d_in[8];
    const float* l2s = (const float*)d_in[9];
    const float* l2b = (const float*)d_in[10];
    const float* Wo  = (const float*)d_in[11];
    const float* bo  = (const float*)d_in[12];
    float* out = (float*)d_out;

    cudaFuncSetAttribute(gemm_qkv_kernel,
                         cudaFuncAttributeMaxDynamicSharedMemorySize, GSMEM);
    cudaFuncSetAttribute(gemm_out_kernel,
                         cudaFuncAttributeMaxDynamicSharedMemorySize, GSMEM);

    void *w2, *wo2;
    cudaGetSymbolAddress(&w2, g_W2);
    cudaGetSymbolAddress(&wo2, g_Wo2);

    dim3 tb(32, 8);
    const size_t WSZ = (size_t)Ff * K2g;
    // Wq/Wk/Wv: fp32 [2048][16384] -> bf16 [16384][3*2048]
    transpose_split_kernel<<<dim3(512, 64), tb>>>(Wq, (__nv_bfloat16*)w2, Kq, Ff);
    transpose_split_kernel<<<dim3(512, 64), tb>>>(Wk, (__nv_bfloat16*)w2 + WSZ, Kq, Ff);
    transpose_split_kernel<<<dim3(512, 64), tb>>>(Wv, (__nv_bfloat16*)w2 + 2 * WSZ, Kq, Ff);
    // Wo: fp32 [16384][2048] -> bf16 [2048][3*16384]
    transpose_split_kernel<<<dim3(64, 512), tb>>>(Wo, (__nv_bfloat16*)wo2, Kf, Nfin);

    ln_im2col_kernel<<<(Bb * Hh * Ww * 32) / 256, 256>>>(x, l1s, l1b);

    dim3 gq(16, 128, 3);
    gemm_qkv_kernel<<<gq, 256, GSMEM>>>(bq, bk, bv);

    dim3 ga(Mm, HEADS);
    attn_kernel<<<ga, 256>>>(l2s, l2b);

    dim3 go(16, 16);
    gemm_out_kernel<<<go, 256, GSMEM>>>(bo, x, out);
}